// round 2
// baseline (speedup 1.0000x reference)
#include <cuda_runtime.h>
#include <math.h>
#include <stdint.h>

#define Bq 16
#define Tq 512
#define Eq 100
#define Hq 500
#define G4 2000
#define NT 32
#define NEGV (-10000.0f)

#define RBLK 125
#define RTHR 128

// ---------------- device scratch (no allocations allowed) ----------------
__device__ float g_xs[Tq * Bq * Eq];                    // [t][b][e]
__device__ float g_A0[2u * Tq * Bq * G4];               // input proj layer0, per dir
__device__ float g_A1[2u * Tq * Bq * G4];               // input proj layer1, per dir
__device__ float g_out0[Tq * Bq * 2 * Hq];              // [t][b][dir*H + j]
__device__ float g_out1[Tq * Bq * 2 * Hq];
__device__ float g_y[Tq * Bq * NT];                     // emissions, row = t*B+b
__device__ float g_hbuf[2 * 2 * Bq * 512];              // [d][pp][b][512]
__device__ float g_gold[Bq];
__device__ float g_Z[Bq];
__device__ unsigned g_bar;

// ---------------- helpers ----------------
__device__ __forceinline__ float sigm_f(float v) {
    return __fdividef(1.0f, 1.0f + __expf(-v));
}
__device__ __forceinline__ float tanh_f(float v) {
    return 1.0f - __fdividef(2.0f, __expf(2.0f * v) + 1.0f);
}

__global__ void k_reset() { g_bar = 0u; }

// ---------------- embedding: xs[t][b][e] = embed_W[x[b][t]][e] ----------------
__global__ void k_embed(const int* __restrict__ x, const float* __restrict__ embw) {
    int idx = blockIdx.x * blockDim.x + threadIdx.x;
    if (idx >= Tq * Bq * Eq) return;
    int e = idx % Eq;
    int rb = idx / Eq;
    int b = rb % Bq;
    int t = rb / Bq;
    int row = x[b * Tq + t];
    g_xs[idx] = embw[(size_t)row * Eq + e];
}

// ---------------- tiled fp32 GEMM: C[d][M,N] = X[M,K] @ W[d][N,K]^T + b1[d]+b2[d] ----------------
// lay==0: X=g_xs (K=100), C=g_A0 ; lay==1: X=g_out0 (K=1000), C=g_A1
__global__ __launch_bounds__(256) void k_gemm(int lay,
                                              const float* __restrict__ W,
                                              const float* __restrict__ b1,
                                              const float* __restrict__ b2) {
    const int M = Tq * Bq;
    const int N = G4;
    const int K = (lay == 0) ? Eq : (2 * Hq);
    const float* X = (lay == 0) ? g_xs : g_out0;
    float* C = (lay == 0) ? g_A0 : g_A1;

    __shared__ float sX[16][64];
    __shared__ float sW[16][64];

    int d = blockIdx.z;
    const float* Wd = W + (size_t)d * N * K;
    const float* b1d = b1 + (size_t)d * N;
    const float* b2d = b2 + (size_t)d * N;
    float* Cd = C + (size_t)d * M * N;

    int m0 = blockIdx.y * 64, n0 = blockIdx.x * 64;
    int tid = threadIdx.x;
    int lr = tid >> 2;          // 0..63
    int lc = (tid & 3) * 4;     // 0,4,8,12
    int tx = tid & 15, ty = tid >> 4;

    float acc[4][4];
#pragma unroll
    for (int i = 0; i < 4; i++)
#pragma unroll
        for (int j = 0; j < 4; j++) acc[i][j] = 0.0f;

    for (int kt = 0; kt < K; kt += 16) {
        float4 xv = make_float4(0.f, 0.f, 0.f, 0.f);
        if (kt + lc < K) xv = *(const float4*)&X[(size_t)(m0 + lr) * K + kt + lc];
        float4 wv = make_float4(0.f, 0.f, 0.f, 0.f);
        if ((n0 + lr) < N && (kt + lc) < K) wv = *(const float4*)&Wd[(size_t)(n0 + lr) * K + kt + lc];
        __syncthreads();
        sX[lc + 0][lr] = xv.x; sX[lc + 1][lr] = xv.y; sX[lc + 2][lr] = xv.z; sX[lc + 3][lr] = xv.w;
        sW[lc + 0][lr] = wv.x; sW[lc + 1][lr] = wv.y; sW[lc + 2][lr] = wv.z; sW[lc + 3][lr] = wv.w;
        __syncthreads();
#pragma unroll
        for (int kk = 0; kk < 16; kk++) {
            float4 xm = *(const float4*)&sX[kk][ty * 4];
            float4 wn = *(const float4*)&sW[kk][tx * 4];
            float xr[4] = {xm.x, xm.y, xm.z, xm.w};
            float wr[4] = {wn.x, wn.y, wn.z, wn.w};
#pragma unroll
            for (int i = 0; i < 4; i++)
#pragma unroll
                for (int j = 0; j < 4; j++)
                    acc[i][j] = fmaf(xr[i], wr[j], acc[i][j]);
        }
    }

#pragma unroll
    for (int i = 0; i < 4; i++) {
        int row = m0 + ty * 4 + i;
#pragma unroll
        for (int j = 0; j < 4; j++) {
            int col = n0 + tx * 4 + j;
            if (col < N)
                Cd[(size_t)row * N + col] = acc[i][j] + b1d[col] + b2d[col];
        }
    }
}

// ---------------- persistent bidirectional LSTM layer ----------------
// 125 blocks x 128 threads; block owns hidden units j0..j0+3 for BOTH directions.
// thread: d = tid>>6, jj = (tid>>4)&3, b = tid&15 — computes 4 gate dots of length 500.
__device__ __forceinline__ void grid_barrier(unsigned* epoch) {
    __syncthreads();
    if (threadIdx.x == 0) {
        __threadfence();
        *epoch += RBLK;
        atomicAdd(&g_bar, 1u);
        while (atomicAdd(&g_bar, 0u) < *epoch) { __nanosleep(32); }
        __threadfence();
    }
    __syncthreads();
}

__global__ __launch_bounds__(RTHR, 1) void k_lstm(int lay,
                                                  const float* __restrict__ Whh,
                                                  const float* __restrict__ h0,
                                                  const float* __restrict__ c0,
                                                  const int* __restrict__ x) {
    extern __shared__ float sm[];
    float* sW = sm;          // [d][jj][g][500]  -> 16000 floats
    float* sh = sm + 16000;  // [d][b][500]      -> 16000 floats

    const float* A = (lay == 0) ? g_A0 : g_A1;
    float* outp = (lay == 0) ? g_out0 : g_out1;
    const int hbase = lay * 2;

    int tid = threadIdx.x;
    int d = tid >> 6;
    int jj = (tid >> 4) & 3;
    int b = tid & 15;
    int j0 = blockIdx.x * 4;
    int j = j0 + jj;

    // load Whh slices: sW[((d*4+jj)*4+g)*500 + i]
    for (int idx = tid; idx < 16000; idx += RTHR) {
        int dd = idx / 8000;
        int r = idx % 8000;
        int jg = r / 500;
        int i = r % 500;
        int jjj = jg >> 2;
        int g = jg & 3;
        sW[idx] = Whh[((size_t)dd * G4 + g * Hq + (j0 + jjj)) * Hq + i];
    }

    float hreg = h0[((size_t)(hbase + d) * Bq + b) * Hq + j];
    float creg = c0[((size_t)(hbase + d) * Bq + b) * Hq + j];

    // publish initial h to ping-pong buffer 0
    g_hbuf[((d * 2 + 0) * Bq + b) * 512 + j] = hreg;
    unsigned epoch = 0;
    grid_barrier(&epoch);

    const float* Ad = A + (size_t)d * Tq * Bq * G4;
    int base = ((d * 4 + jj) * 4) * 500;
    const float4* w0p = (const float4*)&sW[base + 0];
    const float4* w1p = (const float4*)&sW[base + 500];
    const float4* w2p = (const float4*)&sW[base + 1000];
    const float4* w3p = (const float4*)&sW[base + 1500];

    int pp = 0;
    for (int s = 0; s < Tq; s++) {
        // stage h[d][b][:] from global ping-pong (L2-coherent loads)
        for (int q = tid; q < 4000; q += RTHR) {
            int dd = q / 2000;
            int r = q % 2000;
            int bb = r / 125;
            int i4 = r % 125;
            float4 v = __ldcg((const float4*)&g_hbuf[((dd * 2 + pp) * Bq + bb) * 512 + i4 * 4]);
            *(float4*)&sh[(dd * Bq + bb) * 500 + i4 * 4] = v;
        }
        __syncthreads();

        const float4* hp = (const float4*)&sh[(d * Bq + b) * 500];
        float a0 = 0.f, a1 = 0.f, a2 = 0.f, a3 = 0.f;
#pragma unroll 5
        for (int ii = 0; ii < 125; ii++) {
            float4 hv = hp[ii];
            float4 w0 = w0p[ii], w1 = w1p[ii], w2 = w2p[ii], w3 = w3p[ii];
            a0 = fmaf(hv.x, w0.x, a0); a0 = fmaf(hv.y, w0.y, a0);
            a0 = fmaf(hv.z, w0.z, a0); a0 = fmaf(hv.w, w0.w, a0);
            a1 = fmaf(hv.x, w1.x, a1); a1 = fmaf(hv.y, w1.y, a1);
            a1 = fmaf(hv.z, w1.z, a1); a1 = fmaf(hv.w, w1.w, a1);
            a2 = fmaf(hv.x, w2.x, a2); a2 = fmaf(hv.y, w2.y, a2);
            a2 = fmaf(hv.z, w2.z, a2); a2 = fmaf(hv.w, w2.w, a2);
            a3 = fmaf(hv.x, w3.x, a3); a3 = fmaf(hv.y, w3.y, a3);
            a3 = fmaf(hv.z, w3.z, a3); a3 = fmaf(hv.w, w3.w, a3);
        }

        int t = d ? (Tq - 1 - s) : s;
        size_t arow = ((size_t)t * Bq + b) * G4 + j;
        float gi = a0 + __ldg(&Ad[arow + 0 * Hq]);
        float gf = a1 + __ldg(&Ad[arow + 1 * Hq]);
        float gg = a2 + __ldg(&Ad[arow + 2 * Hq]);
        float go = a3 + __ldg(&Ad[arow + 3 * Hq]);

        float cn = sigm_f(gf) * creg + sigm_f(gi) * tanh_f(gg);
        float hn = sigm_f(go) * tanh_f(cn);

        bool m = x[b * Tq + t] > 0;
        outp[((size_t)t * Bq + b) * (2 * Hq) + d * Hq + j] = m ? hn : 0.0f;
        if (m) { creg = cn; hreg = hn; }

        g_hbuf[((d * 2 + (pp ^ 1)) * Bq + b) * 512 + j] = hreg;
        grid_barrier(&epoch);
        pp ^= 1;
    }
}

// ---------------- output projection: y[row][tag] = out1[row] . W_out[tag] + b_out ----------------
__global__ __launch_bounds__(256) void k_outproj(const float* __restrict__ Wo,
                                                 const float* __restrict__ bo) {
    int r0 = blockIdx.x * 8;
    int tag = threadIdx.x & 31;
    int part = threadIdx.x >> 5;  // 0..7, each covers 125 of 1000
    float acc[8];
#pragma unroll
    for (int r = 0; r < 8; r++) acc[r] = 0.0f;

    const float* w = Wo + (size_t)tag * 1000 + part * 125;
    for (int i = 0; i < 125; i++) {
        float wv = __ldg(&w[i]);
        int col = part * 125 + i;
#pragma unroll
        for (int r = 0; r < 8; r++)
            acc[r] = fmaf(wv, g_out1[(size_t)(r0 + r) * 1000 + col], acc[r]);
    }

    __shared__ float red[8][8][32];
#pragma unroll
    for (int r = 0; r < 8; r++) red[part][r][tag] = acc[r];
    __syncthreads();
    if (part == 0) {
#pragma unroll
        for (int r = 0; r < 8; r++) {
            float s = bo[tag];
#pragma unroll
            for (int p = 0; p < 8; p++) s += red[p][r][tag];
            g_y[(size_t)(r0 + r) * NT + tag] = s;
        }
    }
}

// ---------------- gold path score ----------------
__global__ void k_gold(const int* __restrict__ x, const int* __restrict__ y0,
                       const float* __restrict__ trans) {
    int b = blockIdx.x;
    float s = 0.0f;
    for (int t = threadIdx.x; t < Tq; t += blockDim.x) {
        if (x[b * Tq + t] > 0) {
            int cur = y0[b * Tq + t];
            int prev = (t == 0) ? 1 : y0[b * Tq + t - 1];  // SOS = 1
            s += g_y[((size_t)t * Bq + b) * NT + cur] + trans[cur * NT + prev];
        }
    }
    __shared__ float red[256];
    red[threadIdx.x] = s;
    __syncthreads();
    for (int k = 128; k > 0; k >>= 1) {
        if (threadIdx.x < k) red[threadIdx.x] += red[threadIdx.x + k];
        __syncthreads();
    }
    if (threadIdx.x == 0) g_gold[b] = red[0];
}

// ---------------- CRF forward (log-partition) ----------------
__global__ void k_crf(const int* __restrict__ x, const float* __restrict__ trans) {
    int b = blockIdx.x;
    int tag = threadIdx.x;  // 32 threads
    __shared__ float st[NT * NT];
    __shared__ float ss[NT];
    for (int i = tag; i < NT * NT; i += 32) st[i] = trans[i];

    int len = 0;
    for (int t = tag; t < Tq; t += 32) len += (x[b * Tq + t] > 0) ? 1 : 0;
#pragma unroll
    for (int o = 16; o; o >>= 1) len += __shfl_xor_sync(0xffffffffu, len, o);

    float sc = (tag == 1) ? 0.0f : NEGV;
    ss[tag] = sc;
    __syncwarp();

    for (int t = 0; t < len; t++) {
        float emit = g_y[((size_t)t * Bq + b) * NT + tag];
        float mx = -3.4e38f;
#pragma unroll
        for (int p = 0; p < NT; p++) {
            float v = ss[p] + st[tag * NT + p];
            mx = fmaxf(mx, v);
        }
        float sum = 0.0f;
#pragma unroll
        for (int p = 0; p < NT; p++)
            sum += __expf(ss[p] + st[tag * NT + p] - mx);
        sc = emit + mx + __logf(sum);
        __syncwarp();
        ss[tag] = sc;
        __syncwarp();
    }

    float mx = sc;
#pragma unroll
    for (int o = 16; o; o >>= 1) mx = fmaxf(mx, __shfl_xor_sync(0xffffffffu, mx, o));
    float z;
    if (len < Tq) {
        z = mx + __logf(32.0f);  // score collapses to broadcast max; lse = max + ln(32)
    } else {
        float sum = __expf(sc - mx);
#pragma unroll
        for (int o = 16; o; o >>= 1) sum += __shfl_xor_sync(0xffffffffu, sum, o);
        z = mx + __logf(sum);
    }
    if (tag == 0) g_Z[b] = z;
}

__global__ void k_final(float* __restrict__ out) {
    float s = 0.0f;
    for (int b = 0; b < Bq; b++) s += g_Z[b] - g_gold[b];
    out[0] = s / (float)Bq;
}

// ---------------- host launcher ----------------
extern "C" void kernel_launch(void* const* d_in, const int* in_sizes, int n_in,
                              void* d_out, int out_size) {
    (void)in_sizes; (void)n_in; (void)out_size;
    const int*   x     = (const int*)d_in[0];
    const int*   y0    = (const int*)d_in[1];
    const float* embw  = (const float*)d_in[2];
    const float* Wih0  = (const float*)d_in[3];
    const float* Whh0  = (const float*)d_in[4];
    const float* bih0  = (const float*)d_in[5];
    const float* bhh0  = (const float*)d_in[6];
    const float* Wih1  = (const float*)d_in[7];
    const float* Whh1  = (const float*)d_in[8];
    const float* bih1  = (const float*)d_in[9];
    const float* bhh1  = (const float*)d_in[10];
    const float* W_out = (const float*)d_in[11];
    const float* b_out = (const float*)d_in[12];
    const float* trans = (const float*)d_in[13];
    const float* h0    = (const float*)d_in[14];
    const float* c0    = (const float*)d_in[15];
    float* out = (float*)d_out;

    // allow 128 KB dynamic smem for the recurrence kernel (idempotent)
    cudaFuncSetAttribute(k_lstm, cudaFuncAttributeMaxDynamicSharedMemorySize, 131072);

    // 1. embedding
    k_embed<<<(Tq * Bq * Eq + 255) / 256, 256>>>(x, embw);

    // 2. layer-0 input projections (both dirs)
    {
        dim3 grid((G4 + 63) / 64, (Tq * Bq) / 64, 2);
        k_gemm<<<grid, 256>>>(0, Wih0, bih0, bhh0);
    }

    // 3. layer-0 bidirectional recurrence
    k_reset<<<1, 1>>>();
    k_lstm<<<RBLK, RTHR, 2 * 16000 * sizeof(float)>>>(0, Whh0, h0, c0, x);

    // 4. layer-1 input projections
    {
        dim3 grid((G4 + 63) / 64, (Tq * Bq) / 64, 2);
        k_gemm<<<grid, 256>>>(1, Wih1, bih1, bhh1);
    }

    // 5. layer-1 bidirectional recurrence
    k_reset<<<1, 1>>>();
    k_lstm<<<RBLK, RTHR, 2 * 16000 * sizeof(float)>>>(1, Whh1, h0, c0, x);

    // 6. emissions
    k_outproj<<<(Tq * Bq) / 8, 256>>>(W_out, b_out);

    // 7. gold score + CRF partition + final loss
    k_gold<<<Bq, 256>>>(x, y0, trans);
    k_crf<<<Bq, 32>>>(x, trans);
    k_final<<<1, 1>>>(out);
}